// round 2
// baseline (speedup 1.0000x reference)
#include <cuda_runtime.h>
#include <math.h>

typedef unsigned long long ull;

#define QN 48
#define KN 48
#define SS 192
#define DH 512
#define NL 3
#define DFFN 2048
#define NP (QN*KN)   /* 2304 */

// ---------------- scratch (device globals; no allocations allowed) ----------------
__device__ float g_Qp[NL * QN * SS * DH];   // [i][q][t][e]  56.6 MB
__device__ float g_Kp[NL * KN * SS * DH];   // [i][k][s][e]  56.6 MB
__device__ float g_G [NL * SS * SS];        // sigmoid(score_embed)
__device__ float g_X [NL * NP * 2 * SS];    // pooled features per pair
__device__ float g_Z [NL * NP * 2];         // fc3 partial sums

// ---------------- packed f32x2 helpers (FFMA2) ----------------
__device__ __forceinline__ ull fma2(ull a, ull b, ull c) {
    ull d;
    asm("fma.rn.f32x2 %0, %1, %2, %3;" : "=l"(d) : "l"(a), "l"(b), "l"(c));
    return d;
}
__device__ __forceinline__ ull pack2(float x, float y) {
    ull d;
    asm("mov.b64 %0, {%1, %2};" : "=l"(d) : "f"(x), "f"(y));
    return d;
}
__device__ __forceinline__ void unpack2(ull v, float& x, float& y) {
    asm("mov.b64 {%0, %1}, %2;" : "=f"(x), "=f"(y) : "l"(v));
}

// ---------------- kernel 1: gate sigmoid + zero Z ----------------
__global__ void gate_init_kernel(const float* __restrict__ se) {
    int idx = blockIdx.x * blockDim.x + threadIdx.x;
    if (idx < NL * SS * SS) g_G[idx] = 1.0f / (1.0f + expf(-se[idx]));
    if (idx < NL * NP * 2)  g_Z[idx] = 0.0f;
}

// ---------------- kernel 2: projection GEMM  C[m][n] = A[m][:]·W[n][:] + b[n] ----------------
// A: rows of memory/features (lda = NL*DH, per-layer column slice), W: fc1_w[i] (512x512)
// block tile 128x128, 256 threads, thread tile 8x8, k-chunk 16, f32x2 inner.
__global__ void __launch_bounds__(256)
proj_gemm_kernel(const float* __restrict__ A, const float* __restrict__ W,
                 const float* __restrict__ bias, int dst)
{
    const int i = blockIdx.z;
    const int LDA = NL * DH;
    const float* Ab = A + i * DH;
    const float* Wb = W + (size_t)i * DH * DH;
    const float* bb = bias + i * DH;
    float* Cb = (dst ? g_Kp : g_Qp) + (size_t)i * (QN * SS) * DH;
    const int m0 = blockIdx.y * 128, n0 = blockIdx.x * 128;

    __shared__ __align__(16) float As[16 * 132];
    __shared__ __align__(16) float Bs[16 * 132];

    const int tid = threadIdx.x;
    const int tx = tid & 15, ty = tid >> 4;

    ull acc[8][4];
#pragma unroll
    for (int r = 0; r < 8; r++)
#pragma unroll
        for (int j = 0; j < 4; j++) acc[r][j] = 0ull;

    for (int k0 = 0; k0 < DH; k0 += 16) {
#pragma unroll
        for (int l = 0; l < 2; l++) {
            int idx = tid + l * 256;
            int r = idx >> 2, e4 = idx & 3;
            float4 va = *(const float4*)(Ab + (size_t)(m0 + r) * LDA + k0 + e4 * 4);
            float4 vb = *(const float4*)(Wb + (size_t)(n0 + r) * DH  + k0 + e4 * 4);
            int d = e4 * 4;
            As[(d + 0) * 132 + r] = va.x; As[(d + 1) * 132 + r] = va.y;
            As[(d + 2) * 132 + r] = va.z; As[(d + 3) * 132 + r] = va.w;
            Bs[(d + 0) * 132 + r] = vb.x; Bs[(d + 1) * 132 + r] = vb.y;
            Bs[(d + 2) * 132 + r] = vb.z; Bs[(d + 3) * 132 + r] = vb.w;
        }
        __syncthreads();
#pragma unroll
        for (int d = 0; d < 16; d++) {
            const float* ap = As + d * 132 + ty * 8;
            const float* bp = Bs + d * 132 + tx * 8;
            float4 a0 = *(const float4*)ap;
            float4 a1 = *(const float4*)(ap + 4);
            ulonglong2 bq0 = *(const ulonglong2*)bp;
            ulonglong2 bq1 = *(const ulonglong2*)(bp + 4);
            ull b[4] = { bq0.x, bq0.y, bq1.x, bq1.y };
            float a[8] = { a0.x, a0.y, a0.z, a0.w, a1.x, a1.y, a1.z, a1.w };
#pragma unroll
            for (int r = 0; r < 8; r++) {
                ull ad = pack2(a[r], a[r]);
#pragma unroll
                for (int j = 0; j < 4; j++) acc[r][j] = fma2(ad, b[j], acc[r][j]);
            }
        }
        __syncthreads();
    }

    float bv[8];
#pragma unroll
    for (int j = 0; j < 8; j++) bv[j] = bb[n0 + tx * 8 + j];
#pragma unroll
    for (int r = 0; r < 8; r++) {
        int row = m0 + ty * 8 + r;
        float v0, v1, v2, v3, v4, v5, v6, v7;
        unpack2(acc[r][0], v0, v1); unpack2(acc[r][1], v2, v3);
        unpack2(acc[r][2], v4, v5); unpack2(acc[r][3], v6, v7);
        float4 o0 = { v0 + bv[0], v1 + bv[1], v2 + bv[2], v3 + bv[3] };
        float4 o1 = { v4 + bv[4], v5 + bv[5], v6 + bv[6], v7 + bv[7] };
        *(float4*)(Cb + (size_t)row * DH + n0 + tx * 8)     = o0;
        *(float4*)(Cb + (size_t)row * DH + n0 + tx * 8 + 4) = o1;
    }
}

// ---------------- kernel 3: fused score GEMM + gate + dual max-pool ----------------
// one block per (q,k,i). 384 threads: tx in [0,24) owns 8 s-cols, ty in [0,16) owns 12 t-rows.
__global__ void __launch_bounds__(384)
score_pool_kernel()
{
    const int i = blockIdx.z, q = blockIdx.y, k = blockIdx.x;
    const float* Qb = g_Qp + ((size_t)(i * QN + q)) * SS * DH;
    const float* Kb = g_Kp + ((size_t)(i * KN + k)) * SS * DH;

    __shared__ __align__(16) float sm[7680];
    float* Qs = sm;          // [16][196] k-major, padded
    float* Ks = sm + 3136;

    const int tid = threadIdx.x;
    const int tx = tid % 24;           // s group
    const int ty = tid / 24;           // t group

    ull acc[12][4];
#pragma unroll
    for (int t = 0; t < 12; t++)
#pragma unroll
        for (int j = 0; j < 4; j++) acc[t][j] = 0ull;

    for (int k0 = 0; k0 < DH; k0 += 16) {
#pragma unroll
        for (int l = 0; l < 2; l++) {
            int idx = tid + l * 384;           // 768 float4 per tile
            int r = idx >> 2, e4 = idx & 3;
            float4 va = *(const float4*)(Qb + (size_t)r * DH + k0 + e4 * 4);
            float4 vb = *(const float4*)(Kb + (size_t)r * DH + k0 + e4 * 4);
            int d = e4 * 4;
            Qs[(d + 0) * 196 + r] = va.x; Qs[(d + 1) * 196 + r] = va.y;
            Qs[(d + 2) * 196 + r] = va.z; Qs[(d + 3) * 196 + r] = va.w;
            Ks[(d + 0) * 196 + r] = vb.x; Ks[(d + 1) * 196 + r] = vb.y;
            Ks[(d + 2) * 196 + r] = vb.z; Ks[(d + 3) * 196 + r] = vb.w;
        }
        __syncthreads();
#pragma unroll
        for (int d = 0; d < 16; d++) {
            const float* ap = Qs + d * 196 + ty * 12;
            const float* bp = Ks + d * 196 + tx * 8;
            float4 a0 = *(const float4*)ap;
            float4 a1 = *(const float4*)(ap + 4);
            float4 a2 = *(const float4*)(ap + 8);
            ulonglong2 bq0 = *(const ulonglong2*)bp;
            ulonglong2 bq1 = *(const ulonglong2*)(bp + 4);
            ull b[4] = { bq0.x, bq0.y, bq1.x, bq1.y };
            float a[12] = { a0.x, a0.y, a0.z, a0.w,
                            a1.x, a1.y, a1.z, a1.w,
                            a2.x, a2.y, a2.z, a2.w };
#pragma unroll
            for (int t = 0; t < 12; t++) {
                ull ad = pack2(a[t], a[t]);
#pragma unroll
                for (int j = 0; j < 4; j++) acc[t][j] = fma2(ad, b[j], acc[t][j]);
            }
        }
        __syncthreads();
    }

    // gate + per-thread maxes
    const float* gb = g_G + (size_t)i * SS * SS;
    const int sbase = tx * 8, tbase = ty * 12;
    float m1p[12];                        // max over s, per t
#pragma unroll
    for (int t = 0; t < 12; t++) m1p[t] = -3.402823466e38f;
    float m2p[8];                         // max over t, per s
#pragma unroll
    for (int sj = 0; sj < 8; sj++) {
        int s = sbase + sj;
        const float4* gp = (const float4*)(gb + (size_t)s * SS + tbase);
        float4 gg0 = gp[0], gg1 = gp[1], gg2 = gp[2];
        float gv[12] = { gg0.x, gg0.y, gg0.z, gg0.w,
                         gg1.x, gg1.y, gg1.z, gg1.w,
                         gg2.x, gg2.y, gg2.z, gg2.w };
        float mrow = -3.402823466e38f;
#pragma unroll
        for (int t = 0; t < 12; t++) {
            float vlo, vhi;
            unpack2(acc[t][sj >> 1], vlo, vhi);
            float v = ((sj & 1) ? vhi : vlo) * gv[t];
            m1p[t] = fmaxf(m1p[t], v);
            mrow = fmaxf(mrow, v);
        }
        m2p[sj] = mrow;
    }

    // cross-thread reductions (smem reused after last sync)
    float* red1 = sm;             // [24][192] by tx
    float* red2 = sm + 24 * SS;   // [16][192] by ty
#pragma unroll
    for (int t = 0; t < 12; t++) red1[tx * SS + tbase + t] = m1p[t];
#pragma unroll
    for (int sj = 0; sj < 8; sj++) red2[ty * SS + sbase + sj] = m2p[sj];
    __syncthreads();

    float* xo = g_X + ((size_t)i * NP + (size_t)q * KN + k) * (2 * SS);
    if (tid < SS) {
        float m = red1[tid];
#pragma unroll
        for (int r = 1; r < 24; r++) m = fmaxf(m, red1[r * SS + tid]);
        xo[tid] = m;
    } else {
        int s = tid - SS;
        float m = red2[s];
#pragma unroll
        for (int r = 1; r < 16; r++) m = fmaxf(m, red2[r * SS + s]);
        xo[SS + s] = m;
    }
}

// ---------------- kernel 4: bn1 -> fc2 -> bn2 -> relu -> fc3 row-reduce ----------------
// per layer: rows = 4608 (=2*NP) of X, cols = 2048. block tile 64x128, 256 threads, 4x8/thread.
__global__ void __launch_bounds__(256)
mlp_kernel(const float* __restrict__ w2, const float* __restrict__ b2,
           const float* __restrict__ g2, const float* __restrict__ bb2,
           const float* __restrict__ w3,
           const float* __restrict__ g1, const float* __restrict__ bb1)
{
    const int i = blockIdx.z;
    const int row0 = blockIdx.y * 64;
    const int col0 = blockIdx.x * 128;
    const float scale = 1.0f / sqrtf(1.0f + 1e-5f);
    const float g1c = g1[i] * scale, b1v = bb1[i];
    const float* Xb  = g_X + (size_t)i * NP * 2 * SS;
    const float* W2b = w2  + (size_t)i * DFFN * SS;

    __shared__ __align__(16) float As[16 * 68];
    __shared__ __align__(16) float Bs[16 * 132];
    __shared__ float zsh[64];

    const int tid = threadIdx.x;
    const int tx = tid & 15, ty = tid >> 4;
    if (tid < 64) zsh[tid] = 0.0f;

    ull acc[4][4];
#pragma unroll
    for (int r = 0; r < 4; r++)
#pragma unroll
        for (int j = 0; j < 4; j++) acc[r][j] = 0ull;

    for (int k0 = 0; k0 < SS; k0 += 16) {
        {
            int r = tid >> 2, e4 = tid & 3;   // 256 float4 for A tile
            float4 va = *(const float4*)(Xb + (size_t)(row0 + r) * SS + k0 + e4 * 4);
            va.x = va.x * g1c + b1v; va.y = va.y * g1c + b1v;
            va.z = va.z * g1c + b1v; va.w = va.w * g1c + b1v;
            int d = e4 * 4;
            As[(d + 0) * 68 + r] = va.x; As[(d + 1) * 68 + r] = va.y;
            As[(d + 2) * 68 + r] = va.z; As[(d + 3) * 68 + r] = va.w;
        }
#pragma unroll
        for (int l = 0; l < 2; l++) {
            int idx = tid + l * 256;          // 512 float4 for B tile
            int c = idx >> 2, e4 = idx & 3;
            float4 vb = *(const float4*)(W2b + (size_t)(col0 + c) * SS + k0 + e4 * 4);
            int d = e4 * 4;
            Bs[(d + 0) * 132 + c] = vb.x; Bs[(d + 1) * 132 + c] = vb.y;
            Bs[(d + 2) * 132 + c] = vb.z; Bs[(d + 3) * 132 + c] = vb.w;
        }
        __syncthreads();
#pragma unroll
        for (int d = 0; d < 16; d++) {
            const float* ap = As + d * 68 + ty * 4;
            const float* bp = Bs + d * 132 + tx * 8;
            float4 a0 = *(const float4*)ap;
            ulonglong2 bq0 = *(const ulonglong2*)bp;
            ulonglong2 bq1 = *(const ulonglong2*)(bp + 4);
            ull b[4] = { bq0.x, bq0.y, bq1.x, bq1.y };
            float a[4] = { a0.x, a0.y, a0.z, a0.w };
#pragma unroll
            for (int r = 0; r < 4; r++) {
                ull ad = pack2(a[r], a[r]);
#pragma unroll
                for (int j = 0; j < 4; j++) acc[r][j] = fma2(ad, b[j], acc[r][j]);
            }
        }
        __syncthreads();
    }

    // per-column params
    const int cb = col0 + tx * 8;
    float b2v[8], g2v[8], bb2v[8], w3v[8];
    {
        const float4* p;
        p = (const float4*)(b2  + (size_t)i * DFFN + cb);
        float4 u0 = p[0], u1 = p[1];
        b2v[0]=u0.x; b2v[1]=u0.y; b2v[2]=u0.z; b2v[3]=u0.w;
        b2v[4]=u1.x; b2v[5]=u1.y; b2v[6]=u1.z; b2v[7]=u1.w;
        p = (const float4*)(g2  + (size_t)i * DFFN + cb);
        u0 = p[0]; u1 = p[1];
        g2v[0]=u0.x; g2v[1]=u0.y; g2v[2]=u0.z; g2v[3]=u0.w;
        g2v[4]=u1.x; g2v[5]=u1.y; g2v[6]=u1.z; g2v[7]=u1.w;
        p = (const float4*)(bb2 + (size_t)i * DFFN + cb);
        u0 = p[0]; u1 = p[1];
        bb2v[0]=u0.x; bb2v[1]=u0.y; bb2v[2]=u0.z; bb2v[3]=u0.w;
        bb2v[4]=u1.x; bb2v[5]=u1.y; bb2v[6]=u1.z; bb2v[7]=u1.w;
        p = (const float4*)(w3  + (size_t)i * DFFN + cb);
        u0 = p[0]; u1 = p[1];
        w3v[0]=u0.x; w3v[1]=u0.y; w3v[2]=u0.z; w3v[3]=u0.w;
        w3v[4]=u1.x; w3v[5]=u1.y; w3v[6]=u1.z; w3v[7]=u1.w;
    }

#pragma unroll
    for (int r = 0; r < 4; r++) {
        float zp = 0.0f;
#pragma unroll
        for (int j = 0; j < 4; j++) {
            float y0, y1;
            unpack2(acc[r][j], y0, y1);
            y0 += b2v[2 * j];     y1 += b2v[2 * j + 1];
            float yb0 = y0 * (g2v[2 * j] * scale)     + bb2v[2 * j];
            float yb1 = y1 * (g2v[2 * j + 1] * scale) + bb2v[2 * j + 1];
            if (yb0 > 0.0f) zp += yb0 * w3v[2 * j];
            if (yb1 > 0.0f) zp += yb1 * w3v[2 * j + 1];
        }
        atomicAdd(&zsh[ty * 4 + r], zp);
    }
    __syncthreads();
    if (tid < 64) atomicAdd(&g_Z[(size_t)i * NP * 2 + row0 + tid], zsh[tid]);
}

// ---------------- kernel 5: pair-sum, bn3, layer-sum, decoder norm ----------------
__global__ void final_kernel(const float* __restrict__ fc3_b,
                             const float* __restrict__ bn3_g, const float* __restrict__ bn3_b,
                             const float* __restrict__ norm_g, const float* __restrict__ norm_b,
                             float* __restrict__ out)
{
    int p = blockIdx.x * blockDim.x + threadIdx.x;
    if (p >= NP) return;
    const float scale = 1.0f / sqrtf(1.0f + 1e-5f);
    float acc = 0.0f;
#pragma unroll
    for (int i = 0; i < NL; i++) {
        float u = g_Z[i * NP * 2 + 2 * p] + g_Z[i * NP * 2 + 2 * p + 1] + 2.0f * fc3_b[i];
        acc += u * (bn3_g[i] * scale) + bn3_b[i];
    }
    out[p] = acc * (norm_g[0] * scale) + norm_b[0];
}

// ---------------- launch ----------------
extern "C" void kernel_launch(void* const* d_in, const int* in_sizes, int n_in,
                              void* d_out, int out_size)
{
    (void)in_sizes; (void)n_in; (void)out_size;
    const float* memory_  = (const float*)d_in[0];
    const float* features = (const float*)d_in[1];
    const float* fc1_w  = (const float*)d_in[2];
    const float* fc1_b  = (const float*)d_in[3];
    const float* se     = (const float*)d_in[4];
    const float* bn1_g  = (const float*)d_in[5];
    const float* bn1_b  = (const float*)d_in[6];
    const float* fc2_w  = (const float*)d_in[7];
    const float* fc2_b  = (const float*)d_in[8];
    const float* bn2_g  = (const float*)d_in[9];
    const float* bn2_b  = (const float*)d_in[10];
    const float* fc3_w  = (const float*)d_in[11];
    const float* fc3_b  = (const float*)d_in[12];
    const float* bn3_g  = (const float*)d_in[13];
    const float* bn3_b  = (const float*)d_in[14];
    const float* norm_g = (const float*)d_in[15];
    const float* norm_b = (const float*)d_in[16];
    float* out = (float*)d_out;

    gate_init_kernel<<<(NL * SS * SS + 255) / 256, 256>>>(se);

    dim3 gproj(DH / 128, (QN * SS) / 128, NL);          // (4, 72, 3)
    proj_gemm_kernel<<<gproj, 256>>>(memory_,  fc1_w, fc1_b, 0);
    proj_gemm_kernel<<<gproj, 256>>>(features, fc1_w, fc1_b, 1);

    score_pool_kernel<<<dim3(KN, QN, NL), 384>>>();

    mlp_kernel<<<dim3(DFFN / 128, (2 * NP) / 64, NL), 256>>>(
        fc2_w, fc2_b, bn2_g, bn2_b, fc3_w, bn1_g, bn1_b);

    final_kernel<<<(NP + 255) / 256, 256>>>(fc3_b, bn3_g, bn3_b, norm_g, norm_b, out);
}

// round 5
// speedup vs baseline: 2.3034x; 2.3034x over previous
#include <cuda_runtime.h>
#include <cuda_bf16.h>
#include <math.h>
#include <stdint.h>

typedef unsigned long long ull;

#define QN 48
#define KN 48
#define SS 192
#define DH 512
#define NL 3
#define DFFN 2048
#define NP (QN*KN)   /* 2304 */
#define KC 1536      /* concatenated K dim: [hi|hi|lo] x [hi|lo|hi] */
#define ROWB 3072    /* bytes per row = KC * 2 */

// ---------------- scratch (device globals) ----------------
__device__ uint4  g_Qc[(size_t)NL*QN*SS*ROWB/16];   // 84.9 MB bf16 triplets (query)
__device__ uint4  g_Kc[(size_t)NL*KN*SS*ROWB/16];   // 84.9 MB bf16 triplets (key)
__device__ float g_G [NL * SS * SS];
__device__ float g_X [NL * NP * 2 * SS];
__device__ float g_Z [NL * NP * 2];

// ---------------- packed f32x2 helpers ----------------
__device__ __forceinline__ ull fma2(ull a, ull b, ull c) {
    ull d; asm("fma.rn.f32x2 %0, %1, %2, %3;" : "=l"(d) : "l"(a), "l"(b), "l"(c)); return d;
}
__device__ __forceinline__ ull pack2(float x, float y) {
    ull d; asm("mov.b64 %0, {%1, %2};" : "=l"(d) : "f"(x), "f"(y)); return d;
}
__device__ __forceinline__ void unpack2(ull v, float& x, float& y) {
    asm("mov.b64 {%0, %1}, %2;" : "=f"(x), "=f"(y) : "l"(v));
}
__device__ __forceinline__ uint32_t smem_u32(const void* p) {
    uint32_t a;
    asm("{ .reg .u64 t; cvta.to.shared.u64 t, %1; cvt.u32.u64 %0, t; }" : "=r"(a) : "l"(p));
    return a;
}

// ---------------- mma / ldmatrix wrappers ----------------
__device__ __forceinline__ void mma_bf16(float* d, const uint32_t* a, uint32_t b0, uint32_t b1) {
    asm volatile("mma.sync.aligned.m16n8k16.row.col.f32.bf16.bf16.f32 "
                 "{%0,%1,%2,%3}, {%4,%5,%6,%7}, {%8,%9}, {%0,%1,%2,%3};"
                 : "+f"(d[0]), "+f"(d[1]), "+f"(d[2]), "+f"(d[3])
                 : "r"(a[0]), "r"(a[1]), "r"(a[2]), "r"(a[3]), "r"(b0), "r"(b1));
}
__device__ __forceinline__ void ldsm_x4(uint32_t* r, uint32_t addr) {
    asm volatile("ldmatrix.sync.aligned.m8n8.x4.shared.b16 {%0,%1,%2,%3}, [%4];"
                 : "=r"(r[0]), "=r"(r[1]), "=r"(r[2]), "=r"(r[3]) : "r"(addr));
}

// ---------------- kernel 1: gate sigmoid + zero Z ----------------
__global__ void gate_init_kernel(const float* __restrict__ se) {
    int idx = blockIdx.x * blockDim.x + threadIdx.x;
    if (idx < NL * SS * SS) g_G[idx] = 1.0f / (1.0f + expf(-se[idx]));
    if (idx < NL * NP * 2)  g_Z[idx] = 0.0f;
}

// ---------------- kernel 2: projection GEMM -> bf16 hi/lo triplets ----------------
__global__ void __launch_bounds__(256)
proj_gemm_kernel(const float* __restrict__ A, const float* __restrict__ W,
                 const float* __restrict__ bias, int dst)
{
    const int i = blockIdx.z;
    const int LDA = NL * DH;
    const float* Ab = A + i * DH;
    const float* Wb = W + (size_t)i * DH * DH;
    const float* bb = bias + i * DH;
    char* outBase = (char*)(dst ? g_Kc : g_Qc) + (size_t)(i * QN * SS) * ROWB;
    const int m0 = blockIdx.y * 128, n0 = blockIdx.x * 128;

    __shared__ __align__(16) float As[16 * 132];
    __shared__ __align__(16) float Bs[16 * 132];

    const int tid = threadIdx.x;
    const int tx = tid & 15, ty = tid >> 4;

    ull acc[8][4];
#pragma unroll
    for (int r = 0; r < 8; r++)
#pragma unroll
        for (int j = 0; j < 4; j++) acc[r][j] = 0ull;

    for (int k0 = 0; k0 < DH; k0 += 16) {
#pragma unroll
        for (int l = 0; l < 2; l++) {
            int idx = tid + l * 256;
            int r = idx >> 2, e4 = idx & 3;
            float4 va = *(const float4*)(Ab + (size_t)(m0 + r) * LDA + k0 + e4 * 4);
            float4 vb = *(const float4*)(Wb + (size_t)(n0 + r) * DH  + k0 + e4 * 4);
            int d = e4 * 4;
            As[(d + 0) * 132 + r] = va.x; As[(d + 1) * 132 + r] = va.y;
            As[(d + 2) * 132 + r] = va.z; As[(d + 3) * 132 + r] = va.w;
            Bs[(d + 0) * 132 + r] = vb.x; Bs[(d + 1) * 132 + r] = vb.y;
            Bs[(d + 2) * 132 + r] = vb.z; Bs[(d + 3) * 132 + r] = vb.w;
        }
        __syncthreads();
#pragma unroll
        for (int d = 0; d < 16; d++) {
            const float* ap = As + d * 132 + ty * 8;
            const float* bp = Bs + d * 132 + tx * 8;
            float4 a0 = *(const float4*)ap;
            float4 a1 = *(const float4*)(ap + 4);
            ulonglong2 bq0 = *(const ulonglong2*)bp;
            ulonglong2 bq1 = *(const ulonglong2*)(bp + 4);
            ull b[4] = { bq0.x, bq0.y, bq1.x, bq1.y };
            float a[8] = { a0.x, a0.y, a0.z, a0.w, a1.x, a1.y, a1.z, a1.w };
#pragma unroll
            for (int r = 0; r < 8; r++) {
                ull ad = pack2(a[r], a[r]);
#pragma unroll
                for (int j = 0; j < 4; j++) acc[r][j] = fma2(ad, b[j], acc[r][j]);
            }
        }
        __syncthreads();
    }

    float bv[8];
#pragma unroll
    for (int j = 0; j < 8; j++) bv[j] = bb[n0 + tx * 8 + j];
#pragma unroll
    for (int r = 0; r < 8; r++) {
        int row = m0 + ty * 8 + r;
        float v[8];
        unpack2(acc[r][0], v[0], v[1]); unpack2(acc[r][1], v[2], v[3]);
        unpack2(acc[r][2], v[4], v[5]); unpack2(acc[r][3], v[6], v[7]);
        uint32_t hi[4], lo[4];
#pragma unroll
        for (int j = 0; j < 4; j++) {
            float a = v[2*j]   + bv[2*j];
            float b = v[2*j+1] + bv[2*j+1];
            float ha = __bfloat162float(__float2bfloat16(a));
            float hb = __bfloat162float(__float2bfloat16(b));
            __nv_bfloat162 h = __floats2bfloat162_rn(ha, hb);
            __nv_bfloat162 l = __floats2bfloat162_rn(a - ha, b - hb);
            hi[j] = *reinterpret_cast<uint32_t*>(&h);
            lo[j] = *reinterpret_cast<uint32_t*>(&l);
        }
        uint4 H = { hi[0], hi[1], hi[2], hi[3] };
        uint4 L = { lo[0], lo[1], lo[2], lo[3] };
        char* rp = outBase + (size_t)row * ROWB + (size_t)(n0 + tx * 8) * 2;
        *(uint4*)(rp)        = H;                 // slot 0: hi
        if (dst == 0) {                           // query: [hi, hi, lo]
            *(uint4*)(rp + 1024) = H;
            *(uint4*)(rp + 2048) = L;
        } else {                                  // key:   [hi, lo, hi]
            *(uint4*)(rp + 1024) = L;
            *(uint4*)(rp + 2048) = H;
        }
    }
}

// ---------------- kernel 3: HMMA score GEMM + gate + dual max-pool ----------------
#define STAGES 4
#define CHUNK_B 128          /* 64 bf16 per row per chunk */
#define NCHUNK 24            /* 3072 B / 128 B */
#define TILE_A 24576         /* 192 rows x 128B */
#define STAGE_BYTES 49152
#define SM_BASE 1024
#define SMEM_TOTAL_SCORE (SM_BASE + STAGES * STAGE_BYTES)   /* 197632 */

__global__ void __launch_bounds__(384, 1)
score_mma_kernel()
{
    extern __shared__ __align__(128) char dsm[];
    const int i = blockIdx.z, q = blockIdx.y, k = blockIdx.x;
    const int tid = threadIdx.x;
    const int wid = tid >> 5;
    const int lane = tid & 31;
    uint32_t sb = smem_u32(dsm);

    const char* aG = (const char*)g_Qc + (size_t)((i * QN + q) * SS) * ROWB;
    const char* bG = (const char*)g_Kc + (size_t)((i * KN + k) * SS) * ROWB;

    // warp tile: m0 rows (64), n0 cols (48)
    const int m0 = (wid >> 2) * 64;
    const int n0 = (wid & 3) * 48;

    // precomputed swizzled ldmatrix lane offsets (stage-relative); ks advances via ^ (ks<<5)
    uint32_t baseA[4], baseB[3];
#pragma unroll
    for (int mi = 0; mi < 4; mi++) {
        uint32_t row = (uint32_t)(m0 + mi * 16 + (lane & 15));
        uint32_t off = row * 128 + ((lane >> 4) << 4);
        baseA[mi] = off ^ ((off >> 3) & 0x70);
    }
#pragma unroll
    for (int nt = 0; nt < 3; nt++) {
        uint32_t row = (uint32_t)(n0 + nt * 16 + (lane & 7) + ((lane >> 4) << 3));
        uint32_t off = row * 128 + (((lane >> 3) & 1) << 4);
        baseB[nt] = TILE_A + (off ^ ((off >> 3) & 0x70));
    }

    float acc[4][6][4];
#pragma unroll
    for (int mi = 0; mi < 4; mi++)
#pragma unroll
        for (int ni = 0; ni < 6; ni++)
#pragma unroll
            for (int j = 0; j < 4; j++) acc[mi][ni][j] = 0.0f;

    // producer: one 64-col chunk (A + B tiles), SW128 swizzle
    auto load_stage = [&](int c) {
        uint32_t base = sb + SM_BASE + (c & (STAGES - 1)) * STAGE_BYTES;
#pragma unroll
        for (int l = 0; l < 8; l++) {
            int idx = tid + l * 384;            // 0..3071 16B units
            int isB = idx >= 1536;
            int j = isB ? idx - 1536 : idx;
            int r = j >> 3, g = j & 7;
            uint32_t off = (uint32_t)(r * 128 + g * 16);
            off ^= (off >> 3) & 0x70;
            uint32_t dst = base + (isB ? TILE_A : 0) + off;
            const void* src = (const void*)((isB ? bG : aG) + (size_t)r * ROWB + c * CHUNK_B + g * 16);
            asm volatile("cp.async.cg.shared.global [%0], [%1], 16;" :: "r"(dst), "l"(src) : "memory");
        }
        asm volatile("cp.async.commit_group;" ::: "memory");
    };

#pragma unroll
    for (int p = 0; p < STAGES - 1; p++) load_stage(p);

    for (int it = 0; it < NCHUNK; it++) {
        if (it + STAGES - 1 < NCHUNK) load_stage(it + STAGES - 1);
        if (it < NCHUNK - 3)       asm volatile("cp.async.wait_group 3;" ::: "memory");
        else if (it == NCHUNK - 3) asm volatile("cp.async.wait_group 2;" ::: "memory");
        else if (it == NCHUNK - 2) asm volatile("cp.async.wait_group 1;" ::: "memory");
        else                       asm volatile("cp.async.wait_group 0;" ::: "memory");
        __syncthreads();

        uint32_t stage = sb + SM_BASE + (it & (STAGES - 1)) * STAGE_BYTES;
#pragma unroll
        for (int ks = 0; ks < 4; ks++) {
            uint32_t kx = (uint32_t)(ks << 5);
            uint32_t a[4][4], b[3][4];
#pragma unroll
            for (int mi = 0; mi < 4; mi++) ldsm_x4(a[mi], stage + (baseA[mi] ^ kx));
#pragma unroll
            for (int nt = 0; nt < 3; nt++) ldsm_x4(b[nt], stage + (baseB[nt] ^ kx));
#pragma unroll
            for (int mi = 0; mi < 4; mi++) {
#pragma unroll
                for (int nt = 0; nt < 3; nt++) {
                    mma_bf16(acc[mi][2 * nt],     a[mi], b[nt][0], b[nt][1]);
                    mma_bf16(acc[mi][2 * nt + 1], a[mi], b[nt][2], b[nt][3]);
                }
            }
        }
        __syncthreads();
    }

    // ---- epilogue: gate + dual max-pool (score[t][s], gate[s][t]) ----
    const float* gb = g_G + (size_t)i * SS * SS;
    const int g8 = lane >> 2, t4 = lane & 3;
    float rmax[8], cmax[12];
#pragma unroll
    for (int j = 0; j < 8; j++)  rmax[j] = -3.402823466e38f;
#pragma unroll
    for (int j = 0; j < 12; j++) cmax[j] = -3.402823466e38f;

#pragma unroll
    for (int mi = 0; mi < 4; mi++) {
        int r0 = m0 + mi * 16 + g8;
        int r1 = r0 + 8;
#pragma unroll
        for (int ni = 0; ni < 6; ni++) {
            int c0 = n0 + ni * 8 + t4 * 2;
            int c1 = c0 + 1;
            float v00 = acc[mi][ni][0] * __ldg(gb + (size_t)c0 * SS + r0);
            float v01 = acc[mi][ni][1] * __ldg(gb + (size_t)c1 * SS + r0);
            float v10 = acc[mi][ni][2] * __ldg(gb + (size_t)c0 * SS + r1);
            float v11 = acc[mi][ni][3] * __ldg(gb + (size_t)c1 * SS + r1);
            rmax[mi * 2]     = fmaxf(rmax[mi * 2],     fmaxf(v00, v01));
            rmax[mi * 2 + 1] = fmaxf(rmax[mi * 2 + 1], fmaxf(v10, v11));
            cmax[ni * 2]     = fmaxf(cmax[ni * 2],     fmaxf(v00, v10));
            cmax[ni * 2 + 1] = fmaxf(cmax[ni * 2 + 1], fmaxf(v01, v11));
        }
    }
    // rows shared across t4 (lanes ^1, ^2); cols shared across g8 (lanes ^4, ^8, ^16)
#pragma unroll
    for (int m = 1; m <= 2; m <<= 1)
#pragma unroll
        for (int j = 0; j < 8; j++)
            rmax[j] = fmaxf(rmax[j], __shfl_xor_sync(0xffffffffu, rmax[j], m));
#pragma unroll
    for (int m = 4; m <= 16; m <<= 1)
#pragma unroll
        for (int j = 0; j < 12; j++)
            cmax[j] = fmaxf(cmax[j], __shfl_xor_sync(0xffffffffu, cmax[j], m));

    float* red1 = (float*)(dsm + SM_BASE);          // [4][192] by nw
    float* red2 = red1 + 4 * SS;                    // [3][192] by mw
    const int mw = wid >> 2, nw = wid & 3;
    if (t4 == 0) {
#pragma unroll
        for (int j = 0; j < 8; j++)
            red1[nw * SS + m0 + (j >> 1) * 16 + g8 + (j & 1) * 8] = rmax[j];
    }
    if (g8 == 0) {
#pragma unroll
        for (int j = 0; j < 12; j++)
            red2[mw * SS + n0 + (j >> 1) * 8 + t4 * 2 + (j & 1)] = cmax[j];
    }
    __syncthreads();

    float* xo = g_X + ((size_t)i * NP + (size_t)q * KN + k) * (2 * SS);
    if (tid < SS) {
        float m = red1[tid];
        m = fmaxf(m, red1[SS + tid]);
        m = fmaxf(m, red1[2 * SS + tid]);
        m = fmaxf(m, red1[3 * SS + tid]);
        xo[tid] = m;
    } else {
        int s = tid - SS;
        float m = red2[s];
        m = fmaxf(m, red2[SS + s]);
        m = fmaxf(m, red2[2 * SS + s]);
        xo[SS + s] = m;
    }
}

// ---------------- kernel 4: bn1 -> fc2 -> bn2 -> relu -> fc3 row-reduce ----------------
__global__ void __launch_bounds__(256)
mlp_kernel(const float* __restrict__ w2, const float* __restrict__ b2,
           const float* __restrict__ g2, const float* __restrict__ bb2,
           const float* __restrict__ w3,
           const float* __restrict__ g1, const float* __restrict__ bb1)
{
    const int i = blockIdx.z;
    const int row0 = blockIdx.y * 64;
    const int col0 = blockIdx.x * 128;
    const float scale = 1.0f / sqrtf(1.0f + 1e-5f);
    const float g1c = g1[i] * scale, b1v = bb1[i];
    const float* Xb  = g_X + (size_t)i * NP * 2 * SS;
    const float* W2b = w2  + (size_t)i * DFFN * SS;

    __shared__ __align__(16) float As[16 * 68];
    __shared__ __align__(16) float Bs[16 * 132];
    __shared__ float zsh[64];

    const int tid = threadIdx.x;
    const int tx = tid & 15, ty = tid >> 4;
    if (tid < 64) zsh[tid] = 0.0f;

    ull acc[4][4];
#pragma unroll
    for (int r = 0; r < 4; r++)
#pragma unroll
        for (int j = 0; j < 4; j++) acc[r][j] = 0ull;

    for (int k0 = 0; k0 < SS; k0 += 16) {
        {
            int r = tid >> 2, e4 = tid & 3;
            float4 va = *(const float4*)(Xb + (size_t)(row0 + r) * SS + k0 + e4 * 4);
            va.x = va.x * g1c + b1v; va.y = va.y * g1c + b1v;
            va.z = va.z * g1c + b1v; va.w = va.w * g1c + b1v;
            int d = e4 * 4;
            As[(d + 0) * 68 + r] = va.x; As[(d + 1) * 68 + r] = va.y;
            As[(d + 2) * 68 + r] = va.z; As[(d + 3) * 68 + r] = va.w;
        }
#pragma unroll
        for (int l = 0; l < 2; l++) {
            int idx = tid + l * 256;
            int c = idx >> 2, e4 = idx & 3;
            float4 vb = *(const float4*)(W2b + (size_t)(col0 + c) * SS + k0 + e4 * 4);
            int d = e4 * 4;
            Bs[(d + 0) * 132 + c] = vb.x; Bs[(d + 1) * 132 + c] = vb.y;
            Bs[(d + 2) * 132 + c] = vb.z; Bs[(d + 3) * 132 + c] = vb.w;
        }
        __syncthreads();
#pragma unroll
        for (int d = 0; d < 16; d++) {
            const float* ap = As + d * 68 + ty * 4;
            const float* bp = Bs + d * 132 + tx * 8;
            float4 a0 = *(const float4*)ap;
            ulonglong2 bq0 = *(const ulonglong2*)bp;
            ulonglong2 bq1 = *(const ulonglong2*)(bp + 4);
            ull b[4] = { bq0.x, bq0.y, bq1.x, bq1.y };
            float a[4] = { a0.x, a0.y, a0.z, a0.w };
#pragma unroll
            for (int r = 0; r < 4; r++) {
                ull ad = pack2(a[r], a[r]);
#pragma unroll
                for (int j = 0; j < 4; j++) acc[r][j] = fma2(ad, b[j], acc[r][j]);
            }
        }
        __syncthreads();
    }

    const int cb = col0 + tx * 8;
    float b2v[8], g2v[8], bb2v[8], w3v[8];
    {
        const float4* p;
        p = (const float4*)(b2  + (size_t)i * DFFN + cb);
        float4 u0 = p[0], u1 = p[1];
        b2v[0]=u0.x; b2v[1]=u0.y; b2v[2]=u0.z; b2v[3]=u0.w;
        b2v[4]=u1.x; b2v[5]=u1.y; b2v[6]=u1.z; b2v[7]=u1.w;
        p = (const float4*)(g2  + (size_t)i * DFFN + cb);
        u0 = p[0]; u1 = p[1];
        g2v[0]=u0.x; g2v[1]=u0.y; g2v[2]=u0.z; g2v[3]=u0.w;
        g2v[4]=u1.x; g2v[5]=u1.y; g2v[6]=u1.z; g2v[7]=u1.w;
        p = (const float4*)(bb2 + (size_t)i * DFFN + cb);
        u0 = p[0]; u1 = p[1];
        bb2v[0]=u0.x; bb2v[1]=u0.y; bb2v[2]=u0.z; bb2v[3]=u0.w;
        bb2v[4]=u1.x; bb2v[5]=u1.y; bb2v[6]=u1.z; bb2v[7]=u1.w;
        p = (const float4*)(w3  + (size_t)i * DFFN + cb);
        u0 = p[0]; u1 = p[1];
        w3v[0]=u0.x; w3v[1]=u0.y; w3v[2]=u0.z; w3v[3]=u0.w;
        w3v[4]=u1.x; w3v[5]=u1.y; w3v[6]=u1.z; w3v[7]=u1.w;
    }

#pragma unroll
    for (int r = 0; r < 4; r++) {
        float zp = 0.0f;
#pragma unroll
        for (int j = 0; j < 4; j++) {
            float y0, y1;
            unpack2(acc[r][j], y0, y1);
            y0 += b2v[2 * j];     y1 += b2v[2 * j + 1];
            float yb0 = y0 * (g2v[2 * j] * scale)     + bb2v[2 * j];
            float yb1 = y1 * (g2v[2 * j + 1] * scale) + bb2v[2 * j + 1];
            if (yb0 > 0.0f) zp += yb0 * w3v[2 * j];
            if (yb1 > 0.0f) zp += yb1 * w3v[2 * j + 1];
        }
        atomicAdd(&zsh[ty * 4 + r], zp);
    }
    __syncthreads();
    if (tid < 64) atomicAdd(&g_Z[(size_t)i * NP * 2 + row0 + tid], zsh[tid]);
}

// ---------------- kernel 5: pair-sum, bn3, layer-sum, decoder norm ----------------
__global__ void final_kernel(const float* __restrict__ fc3_b,
                             const float* __restrict__ bn3_g, const float* __restrict__ bn3_b,
                             const float* __restrict__ norm_g, const float* __restrict__ norm_b,
                             float* __restrict__ out)
{
    int p = blockIdx.x * blockDim.x + threadIdx.x;
    if (p >= NP) return;
    const float scale = 1.0f / sqrtf(1.0f + 1e-5f);
    float acc = 0.0f;
#pragma unroll
    for (int i = 0; i < NL; i++) {
        float u = g_Z[i * NP * 2 + 2 * p] + g_Z[i * NP * 2 + 2 * p + 1] + 2.0f * fc3_b[i];
        acc += u * (bn3_g[i] * scale) + bn3_b[i];
    }
    out[p] = acc * (norm_g[0] * scale) + norm_b[0];
}

// ---------------- launch ----------------
extern "C" void kernel_launch(void* const* d_in, const int* in_sizes, int n_in,
                              void* d_out, int out_size)
{
    (void)in_sizes; (void)n_in; (void)out_size;
    const float* memory_  = (const float*)d_in[0];
    const float* features = (const float*)d_in[1];
    const float* fc1_w  = (const float*)d_in[2];
    const float* fc1_b  = (const float*)d_in[3];
    const float* se     = (const float*)d_in[4];
    const float* bn1_g  = (const float*)d_in[5];
    const float* bn1_b  = (const float*)d_in[6];
    const float* fc2_w  = (const float*)d_in[7];
    const float* fc2_b  = (const float*)d_in[8];
    const float* bn2_g  = (const float*)d_in[9];
    const float* bn2_b  = (const float*)d_in[10];
    const float* fc3_w  = (const float*)d_in[11];
    const float* fc3_b  = (const float*)d_in[12];
    const float* bn3_g  = (const float*)d_in[13];
    const float* bn3_b  = (const float*)d_in[14];
    const float* norm_g = (const float*)d_in[15];
    const float* norm_b = (const float*)d_in[16];
    float* out = (float*)d_out;

    cudaFuncSetAttribute(score_mma_kernel,
                         cudaFuncAttributeMaxDynamicSharedMemorySize, SMEM_TOTAL_SCORE);

    gate_init_kernel<<<(NL * SS * SS + 255) / 256, 256>>>(se);

    dim3 gproj(DH / 128, (QN * SS) / 128, NL);
    proj_gemm_kernel<<<gproj, 256>>>(memory_,  fc1_w, fc1_b, 0);
    proj_gemm_kernel<<<gproj, 256>>>(features, fc1_w, fc1_b, 1);

    score_mma_kernel<<<dim3(KN, QN, NL), 384, SMEM_TOTAL_SCORE>>>();

    mlp_kernel<<<dim3(DFFN / 128, (2 * NP) / 64, NL), 256>>>(
        fc2_w, fc2_b, bn2_g, bn2_b, fc3_w, bn1_g, bn1_b);

    final_kernel<<<(NP + 255) / 256, 256>>>(fc3_b, bn3_g, bn3_b, norm_g, norm_b, out);
}